// round 14
// baseline (speedup 1.0000x reference)
#include <cuda_runtime.h>

#define DIM 256
#define PLANE (DIM*DIM)
#define NELEM (DIM*DIM*DIM)

#define HTILES 64          // h tiles of 4 rows (1 row per thread)
#define DCHUNKS 9          // 7 chunks of 28 iters + 2 of 29 (balanced)
#define NBLOCKS (HTILES*DCHUNKS)   // 576 ~ one occ-4 wave (592 slots)

__device__ float g_partials[NBLOCKS];
__device__ unsigned int g_count = 0;   // wraps to 0 each launch via atomicInc

__device__ __forceinline__ float sqrt_approx(float x) {
    float r;
    asm("sqrt.approx.f32 %0, %1;" : "=f"(r) : "f"(x));
    return r;
}

__global__ __launch_bounds__(256, 4)
void grad_loss_fused(const float* __restrict__ x1,
                     const float* __restrict__ x2,
                     float* __restrict__ out) {
    __shared__ float ssum[8];
    __shared__ int s_last;

    const int tx = threadIdx.x;            // 0..63 -> w quad
    const int ty = threadIdx.y;            // 0..3  -> h row
    const int htile = blockIdx.x;          // 0..63
    const int chunk = blockIdx.y;          // 0..8
    const int bid = chunk * HTILES + htile;

    const int h  = 1 + htile * 4 + ty;     // 1..256
    const int w0 = tx * 4;
    // Balanced chunking: chunks 0,1 get 29 iters, chunks 2..8 get 28.
    const int d0    = 1 + chunk * 28 + min(chunk, 2);
    const int niter = 28 + (chunk < 2 ? 1 : 0);

    const bool hcomp = (h <= DIM - 2);     // uniform per warp

    float local = 0.0f;

    if (hcomp) {
        const float wh  = (h == 1 || h == DIM - 2) ? 2.0f : 1.0f;
        const bool  hasl = (tx > 0);
        const bool  hasr = (tx < 63);
        // Folded element weights (wh folded in; wd applied per iteration):
        const float wv0 = hasl ? wh : 0.0f;
        const float wv1 = ((tx == 0)  ? 2.0f : 1.0f) * wh;
        const float wv2 = ((tx == 63) ? 2.0f : 1.0f) * wh;
        const float wv3 = hasr ? wh : 0.0f;

        // q points at (d, h, w0); advance by PLANE per iteration.
        const float* q1 = x1 + d0 * PLANE + h * DIM + w0;
        const float* q2 = x2 + d0 * PLANE + h * DIM + w0;

        // Register window: A = d-1, B = d, C = d+1; D = d+2 prefetched
        // one full iteration ahead. Edge scalars also prefetched at
        // distance 1 (lines are L1-resident from last iter's D prefetch).
        float4 A0 = *(const float4*)(q1 - PLANE);
        float4 A1 = *(const float4*)(q2 - PLANE);
        float4 B0 = *(const float4*)(q1);
        float4 B1 = *(const float4*)(q2);
        float4 C0 = *(const float4*)(q1 + PLANE);
        float4 C1 = *(const float4*)(q2 + PLANE);
        float lf0 = hasl ? q1[-1] : 0.0f;
        float rt0 = hasr ? q1[4]  : 0.0f;
        float lf1 = hasl ? q2[-1] : 0.0f;
        float rt1 = hasr ? q2[4]  : 0.0f;

        int d = d0;
        #pragma unroll 4
        for (int it = 0; it < niter; ++it, ++d, q1 += PLANE, q2 += PLANE) {
            // ---- prefetch plane d+2 center (consumed NEXT iteration) ----
            const int pf = (d + 2 <= DIM - 1) ? 2 * PLANE : PLANE;
            const float4 D0 = *(const float4*)(q1 + pf);
            const float4 D1 = *(const float4*)(q2 + pf);
            // ---- prefetch next iteration's edge scalars (plane d+1) ----
            const float lf0n = hasl ? q1[PLANE - 1] : 0.0f;
            const float rt0n = hasr ? q1[PLANE + 4] : 0.0f;
            const float lf1n = hasl ? q2[PLANE - 1] : 0.0f;
            const float rt1n = hasr ? q2[PLANE + 4] : 0.0f;

            // ---- cache-resident row-neighbor loads for this iteration ----
            const float4 up0 = *(const float4*)(q1 - DIM);
            const float4 dn0 = *(const float4*)(q1 + DIM);
            const float4 up1 = *(const float4*)(q2 - DIM);
            const float4 dn1 = *(const float4*)(q2 + DIM);

            const float wd = (d == 1 || d == DIM - 2) ? 2.0f : 1.0f;

            float gw, gh, gd;
            float m00, m01, m02, m03;
            gw = B0.y - lf0;  gh = dn0.x - up0.x;  gd = C0.x - A0.x;
            m00 = sqrt_approx(gw*gw + gh*gh + gd*gd + 1e-6f);
            gw = B0.z - B0.x; gh = dn0.y - up0.y;  gd = C0.y - A0.y;
            m01 = sqrt_approx(gw*gw + gh*gh + gd*gd + 1e-6f);
            gw = B0.w - B0.y; gh = dn0.z - up0.z;  gd = C0.z - A0.z;
            m02 = sqrt_approx(gw*gw + gh*gh + gd*gd + 1e-6f);
            gw = rt0 - B0.z;  gh = dn0.w - up0.w;  gd = C0.w - A0.w;
            m03 = sqrt_approx(gw*gw + gh*gh + gd*gd + 1e-6f);

            float m10, m11, m12, m13;
            gw = B1.y - lf1;  gh = dn1.x - up1.x;  gd = C1.x - A1.x;
            m10 = sqrt_approx(gw*gw + gh*gh + gd*gd + 1e-6f);
            gw = B1.z - B1.x; gh = dn1.y - up1.y;  gd = C1.y - A1.y;
            m11 = sqrt_approx(gw*gw + gh*gh + gd*gd + 1e-6f);
            gw = B1.w - B1.y; gh = dn1.z - up1.z;  gd = C1.z - A1.z;
            m12 = sqrt_approx(gw*gw + gh*gh + gd*gd + 1e-6f);
            gw = rt1 - B1.z;  gh = dn1.w - up1.w;  gd = C1.w - A1.w;
            m13 = sqrt_approx(gw*gw + gh*gh + gd*gd + 1e-6f);

            float s;
            s = wv0 * fabsf(m00 - m10);
            s = fmaf(wv1, fabsf(m01 - m11), s);
            s = fmaf(wv2, fabsf(m02 - m12), s);
            s = fmaf(wv3, fabsf(m03 - m13), s);
            local = fmaf(wd, s, local);

            // rotate window forward (renamed away by unroll 4)
            A0 = B0; A1 = B1; B0 = C0; B1 = C1; C0 = D0; C1 = D1;
            lf0 = lf0n; rt0 = rt0n; lf1 = lf1n; rt1 = rt1n;
        }
    }

    // ---- block reduction ----
    #pragma unroll
    for (int off = 16; off > 0; off >>= 1)
        local += __shfl_xor_sync(0xffffffffu, local, off);

    const int tid  = ty * 64 + tx;
    const int warp = tid >> 5;
    const int lane = tid & 31;
    if (lane == 0) ssum[warp] = local;
    __syncthreads();

    if (tid == 0) {
        float v = 0.0f;
        #pragma unroll
        for (int i = 0; i < 8; ++i) v += ssum[i];
        g_partials[bid] = v;
        __threadfence();
        unsigned int t = atomicInc(&g_count, NBLOCKS - 1);
        s_last = (t == NBLOCKS - 1);
    }
    __syncthreads();

    // ---- last block finishes the global reduction ----
    if (s_last) {
        __threadfence();
        float s = 0.0f;
        const volatile float* gp = g_partials;
        for (int i = tid; i < NBLOCKS; i += 256)
            s += gp[i];
        #pragma unroll
        for (int off = 16; off > 0; off >>= 1)
            s += __shfl_xor_sync(0xffffffffu, s, off);
        if (lane == 0) ssum[warp] = s;
        __syncthreads();
        if (warp == 0) {
            float v = (lane < 8) ? ssum[lane] : 0.0f;
            #pragma unroll
            for (int off = 4; off > 0; off >>= 1)
                v += __shfl_xor_sync(0xffffffffu, v, off);
            if (lane == 0)
                out[0] = v * (1.0f / (float)NELEM);
        }
    }
}

extern "C" void kernel_launch(void* const* d_in, const int* in_sizes, int n_in,
                              void* d_out, int out_size) {
    const float* x1 = (const float*)d_in[0];
    const float* x2 = (const float*)d_in[1];
    float* out = (float*)d_out;
    (void)in_sizes; (void)n_in; (void)out_size;

    dim3 block(64, 4, 1);
    dim3 grid(HTILES, DCHUNKS, 1);
    grad_loss_fused<<<grid, block>>>(x1, x2, out);
}

// round 15
// speedup vs baseline: 1.2381x; 1.2381x over previous
#include <cuda_runtime.h>

#define DIM 256
#define PLANE (DIM*DIM)
#define NELEM (DIM*DIM*DIM)

#define HTILES 64          // h tiles of 4 rows (1 row per thread)
#define DCHUNKS 9          // 2 chunks of 29 iters + 7 of 28 (balanced)
#define NBLOCKS (HTILES*DCHUNKS)   // 576 ~ one occ-4 wave (592 slots)

__device__ float g_partials[NBLOCKS];
__device__ unsigned int g_count = 0;   // wraps to 0 each launch via atomicInc

__device__ __forceinline__ float sqrt_approx(float x) {
    float r;
    asm("sqrt.approx.f32 %0, %1;" : "=f"(r) : "f"(x));
    return r;
}

__global__ __launch_bounds__(256, 4)
void grad_loss_fused(const float* __restrict__ x1,
                     const float* __restrict__ x2,
                     float* __restrict__ out) {
    __shared__ float ssum[8];
    __shared__ int s_last;

    const int tx = threadIdx.x;            // 0..63 -> w quad
    const int ty = threadIdx.y;            // 0..3  -> h row
    const int htile = blockIdx.x;          // 0..63
    const int chunk = blockIdx.y;          // 0..8
    const int bid = chunk * HTILES + htile;

    const int h  = 1 + htile * 4 + ty;     // 1..256
    const int w0 = tx * 4;
    // Balanced chunking: chunks 0,1 get 29 iters, chunks 2..8 get 28.
    const int d0    = 1 + chunk * 28 + min(chunk, 2);
    const int niter = 28 + (chunk < 2 ? 1 : 0);

    const bool hcomp = (h <= DIM - 2);     // uniform per warp

    float local = 0.0f;

    if (hcomp) {
        const float wh  = (h == 1 || h == DIM - 2) ? 2.0f : 1.0f;
        const bool  hasl = (tx > 0);
        const bool  hasr = (tx < 63);
        // Folded element weights (wh folded in; wd applied per iteration).
        // These are loop-invariant constants — no carried state added.
        const float wv0 = hasl ? wh : 0.0f;
        const float wv1 = ((tx == 0)  ? 2.0f : 1.0f) * wh;
        const float wv2 = ((tx == 63) ? 2.0f : 1.0f) * wh;
        const float wv3 = hasr ? wh : 0.0f;

        // q points at (d, h, w0); advance by PLANE per iteration.
        const float* q1 = x1 + d0 * PLANE + h * DIM + w0;
        const float* q2 = x2 + d0 * PLANE + h * DIM + w0;

        // Register window: A = d-1, B = d, C = d+1; D = d+2 prefetched
        // one full iteration ahead of use.
        float4 A0 = *(const float4*)(q1 - PLANE);
        float4 A1 = *(const float4*)(q2 - PLANE);
        float4 B0 = *(const float4*)(q1);
        float4 B1 = *(const float4*)(q2);
        float4 C0 = *(const float4*)(q1 + PLANE);
        float4 C1 = *(const float4*)(q2 + PLANE);

        int d = d0;
        #pragma unroll 4
        for (int it = 0; it < niter; ++it, ++d, q1 += PLANE, q2 += PLANE) {
            // ---- prefetch plane d+2 (consumed NEXT iteration) ----
            const int pf = (d + 2 <= DIM - 1) ? 2 * PLANE : PLANE;
            const float4 D0 = *(const float4*)(q1 + pf);
            const float4 D1 = *(const float4*)(q2 + pf);

            // ---- cache-resident neighbor loads for this iteration ----
            const float4 up0 = *(const float4*)(q1 - DIM);
            const float4 dn0 = *(const float4*)(q1 + DIM);
            const float4 up1 = *(const float4*)(q2 - DIM);
            const float4 dn1 = *(const float4*)(q2 + DIM);
            const float lf0 = hasl ? q1[-1] : 0.0f;
            const float rt0 = hasr ? q1[4]  : 0.0f;
            const float lf1 = hasl ? q2[-1] : 0.0f;
            const float rt1 = hasr ? q2[4]  : 0.0f;

            const float wd = (d == 1 || d == DIM - 2) ? 2.0f : 1.0f;

            float gw, gh, gd;
            float m00, m01, m02, m03;
            gw = B0.y - lf0;  gh = dn0.x - up0.x;  gd = C0.x - A0.x;
            m00 = sqrt_approx(gw*gw + gh*gh + gd*gd + 1e-6f);
            gw = B0.z - B0.x; gh = dn0.y - up0.y;  gd = C0.y - A0.y;
            m01 = sqrt_approx(gw*gw + gh*gh + gd*gd + 1e-6f);
            gw = B0.w - B0.y; gh = dn0.z - up0.z;  gd = C0.z - A0.z;
            m02 = sqrt_approx(gw*gw + gh*gh + gd*gd + 1e-6f);
            gw = rt0 - B0.z;  gh = dn0.w - up0.w;  gd = C0.w - A0.w;
            m03 = sqrt_approx(gw*gw + gh*gh + gd*gd + 1e-6f);

            float m10, m11, m12, m13;
            gw = B1.y - lf1;  gh = dn1.x - up1.x;  gd = C1.x - A1.x;
            m10 = sqrt_approx(gw*gw + gh*gh + gd*gd + 1e-6f);
            gw = B1.z - B1.x; gh = dn1.y - up1.y;  gd = C1.y - A1.y;
            m11 = sqrt_approx(gw*gw + gh*gh + gd*gd + 1e-6f);
            gw = B1.w - B1.y; gh = dn1.z - up1.z;  gd = C1.z - A1.z;
            m12 = sqrt_approx(gw*gw + gh*gh + gd*gd + 1e-6f);
            gw = rt1 - B1.z;  gh = dn1.w - up1.w;  gd = C1.w - A1.w;
            m13 = sqrt_approx(gw*gw + gh*gh + gd*gd + 1e-6f);

            float s;
            s = wv0 * fabsf(m00 - m10);
            s = fmaf(wv1, fabsf(m01 - m11), s);
            s = fmaf(wv2, fabsf(m02 - m12), s);
            s = fmaf(wv3, fabsf(m03 - m13), s);
            local = fmaf(wd, s, local);

            // rotate window forward (renamed away by unroll 4)
            A0 = B0; A1 = B1; B0 = C0; B1 = C1; C0 = D0; C1 = D1;
        }
    }

    // ---- block reduction ----
    #pragma unroll
    for (int off = 16; off > 0; off >>= 1)
        local += __shfl_xor_sync(0xffffffffu, local, off);

    const int tid  = ty * 64 + tx;
    const int warp = tid >> 5;
    const int lane = tid & 31;
    if (lane == 0) ssum[warp] = local;
    __syncthreads();

    if (tid == 0) {
        float v = 0.0f;
        #pragma unroll
        for (int i = 0; i < 8; ++i) v += ssum[i];
        g_partials[bid] = v;
        __threadfence();
        unsigned int t = atomicInc(&g_count, NBLOCKS - 1);
        s_last = (t == NBLOCKS - 1);
    }
    __syncthreads();

    // ---- last block finishes the global reduction ----
    if (s_last) {
        __threadfence();
        float s = 0.0f;
        const volatile float* gp = g_partials;
        for (int i = tid; i < NBLOCKS; i += 256)
            s += gp[i];
        #pragma unroll
        for (int off = 16; off > 0; off >>= 1)
            s += __shfl_xor_sync(0xffffffffu, s, off);
        if (lane == 0) ssum[warp] = s;
        __syncthreads();
        if (warp == 0) {
            float v = (lane < 8) ? ssum[lane] : 0.0f;
            #pragma unroll
            for (int off = 4; off > 0; off >>= 1)
                v += __shfl_xor_sync(0xffffffffu, v, off);
            if (lane == 0)
                out[0] = v * (1.0f / (float)NELEM);
        }
    }
}

extern "C" void kernel_launch(void* const* d_in, const int* in_sizes, int n_in,
                              void* d_out, int out_size) {
    const float* x1 = (const float*)d_in[0];
    const float* x2 = (const float*)d_in[1];
    float* out = (float*)d_out;
    (void)in_sizes; (void)n_in; (void)out_size;

    dim3 block(64, 4, 1);
    dim3 grid(HTILES, DCHUNKS, 1);
    grad_loss_fused<<<grid, block>>>(x1, x2, out);
}

// round 16
// speedup vs baseline: 1.2422x; 1.0033x over previous
#include <cuda_runtime.h>

#define DIM 256
#define PLANE (DIM*DIM)
#define NELEM (DIM*DIM*DIM)

#define HTILES 64          // h tiles of 4 rows (1 row per thread)
#define DCHUNKS 9          // 2 chunks of 29 iters + 7 of 28 (balanced)
#define NBLOCKS (HTILES*DCHUNKS)   // 576 ~ one occ-4 wave (592 slots)

__device__ float g_partials[NBLOCKS];
__device__ unsigned int g_count = 0;   // wraps to 0 each launch via atomicInc

__device__ __forceinline__ float sqrt_approx(float x) {
    float r;
    asm("sqrt.approx.f32 %0, %1;" : "=f"(r) : "f"(x));
    return r;
}

__global__ __launch_bounds__(256, 4)
void grad_loss_fused(const float* __restrict__ x1,
                     const float* __restrict__ x2,
                     float* __restrict__ out) {
    __shared__ float ssum[8];
    __shared__ int s_last;

    const int tx = threadIdx.x;            // 0..63 -> w quad
    const int ty = threadIdx.y;            // 0..3  -> h row
    const int htile = blockIdx.x;          // 0..63
    const int chunk = blockIdx.y;          // 0..8
    const int bid = chunk * HTILES + htile;

    const int h  = 1 + htile * 4 + ty;     // 1..256
    const int w0 = tx * 4;
    // Balanced chunking: chunks 0,1 get 29 iters, chunks 2..8 get 28.
    const int d0    = 1 + chunk * 28 + min(chunk, 2);
    const int niter = 28 + (chunk < 2 ? 1 : 0);

    const bool hcomp = (h <= DIM - 2);     // uniform per warp

    float local = 0.0f;

    if (hcomp) {
        const float wh  = (h == 1 || h == DIM - 2) ? 2.0f : 1.0f;
        const float wl  = (tx == 0)  ? 2.0f : 1.0f;
        const float wr  = (tx == 63) ? 2.0f : 1.0f;
        const bool  hasl = (tx > 0);
        const bool  hasr = (tx < 63);

        // q points at (d, h, w0); advance by PLANE per iteration.
        const float* q1 = x1 + d0 * PLANE + h * DIM + w0;
        const float* q2 = x2 + d0 * PLANE + h * DIM + w0;

        // Register window: A = d-1, B = d, C = d+1; D = d+2 prefetched
        // one full iteration ahead of use.
        float4 A0 = *(const float4*)(q1 - PLANE);
        float4 A1 = *(const float4*)(q2 - PLANE);
        float4 B0 = *(const float4*)(q1);
        float4 B1 = *(const float4*)(q2);
        float4 C0 = *(const float4*)(q1 + PLANE);
        float4 C1 = *(const float4*)(q2 + PLANE);

        int d = d0;
        #pragma unroll 4
        for (int it = 0; it < niter; ++it, ++d, q1 += PLANE, q2 += PLANE) {
            // ---- prefetch plane d+2 (consumed NEXT iteration) ----
            const int pf = (d + 2 <= DIM - 1) ? 2 * PLANE : PLANE;
            const float4 D0 = *(const float4*)(q1 + pf);
            const float4 D1 = *(const float4*)(q2 + pf);

            // ---- cache-resident neighbor loads for this iteration ----
            const float4 up0 = *(const float4*)(q1 - DIM);
            const float4 dn0 = *(const float4*)(q1 + DIM);
            const float4 up1 = *(const float4*)(q2 - DIM);
            const float4 dn1 = *(const float4*)(q2 + DIM);
            const float lf0 = hasl ? q1[-1] : 0.0f;
            const float rt0 = hasr ? q1[4]  : 0.0f;
            const float lf1 = hasl ? q2[-1] : 0.0f;
            const float rt1 = hasr ? q2[4]  : 0.0f;

            const float wd = (d == 1 || d == DIM - 2) ? 2.0f : 1.0f;

            float gw, gh, gd;
            float m00, m01, m02, m03;
            gw = B0.y - lf0;  gh = dn0.x - up0.x;  gd = C0.x - A0.x;
            m00 = sqrt_approx(gw*gw + gh*gh + gd*gd + 1e-6f);
            gw = B0.z - B0.x; gh = dn0.y - up0.y;  gd = C0.y - A0.y;
            m01 = sqrt_approx(gw*gw + gh*gh + gd*gd + 1e-6f);
            gw = B0.w - B0.y; gh = dn0.z - up0.z;  gd = C0.z - A0.z;
            m02 = sqrt_approx(gw*gw + gh*gh + gd*gd + 1e-6f);
            gw = rt0 - B0.z;  gh = dn0.w - up0.w;  gd = C0.w - A0.w;
            m03 = sqrt_approx(gw*gw + gh*gh + gd*gd + 1e-6f);

            float m10, m11, m12, m13;
            gw = B1.y - lf1;  gh = dn1.x - up1.x;  gd = C1.x - A1.x;
            m10 = sqrt_approx(gw*gw + gh*gh + gd*gd + 1e-6f);
            gw = B1.z - B1.x; gh = dn1.y - up1.y;  gd = C1.y - A1.y;
            m11 = sqrt_approx(gw*gw + gh*gh + gd*gd + 1e-6f);
            gw = B1.w - B1.y; gh = dn1.z - up1.z;  gd = C1.z - A1.z;
            m12 = sqrt_approx(gw*gw + gh*gh + gd*gd + 1e-6f);
            gw = rt1 - B1.z;  gh = dn1.w - up1.w;  gd = C1.w - A1.w;
            m13 = sqrt_approx(gw*gw + gh*gh + gd*gd + 1e-6f);

            float s = 0.0f;
            if (hasl) s += fabsf(m00 - m10);
            s += wl * fabsf(m01 - m11);
            s += wr * fabsf(m02 - m12);
            if (hasr) s += fabsf(m03 - m13);
            local += wd * wh * s;

            // rotate window forward (renamed away by unroll 4)
            A0 = B0; A1 = B1; B0 = C0; B1 = C1; C0 = D0; C1 = D1;
        }
    }

    // ---- block reduction ----
    #pragma unroll
    for (int off = 16; off > 0; off >>= 1)
        local += __shfl_xor_sync(0xffffffffu, local, off);

    const int tid  = ty * 64 + tx;
    const int warp = tid >> 5;
    const int lane = tid & 31;
    if (lane == 0) ssum[warp] = local;
    __syncthreads();

    if (tid == 0) {
        float v = 0.0f;
        #pragma unroll
        for (int i = 0; i < 8; ++i) v += ssum[i];
        g_partials[bid] = v;
        __threadfence();
        unsigned int t = atomicInc(&g_count, NBLOCKS - 1);
        s_last = (t == NBLOCKS - 1);
    }
    __syncthreads();

    // ---- last block finishes the global reduction ----
    if (s_last) {
        __threadfence();
        float s = 0.0f;
        const volatile float* gp = g_partials;
        for (int i = tid; i < NBLOCKS; i += 256)
            s += gp[i];
        #pragma unroll
        for (int off = 16; off > 0; off >>= 1)
            s += __shfl_xor_sync(0xffffffffu, s, off);
        if (lane == 0) ssum[warp] = s;
        __syncthreads();
        if (warp == 0) {
            float v = (lane < 8) ? ssum[lane] : 0.0f;
            #pragma unroll
            for (int off = 4; off > 0; off >>= 1)
                v += __shfl_xor_sync(0xffffffffu, v, off);
            if (lane == 0)
                out[0] = v * (1.0f / (float)NELEM);
        }
    }
}

extern "C" void kernel_launch(void* const* d_in, const int* in_sizes, int n_in,
                              void* d_out, int out_size) {
    const float* x1 = (const float*)d_in[0];
    const float* x2 = (const float*)d_in[1];
    float* out = (float*)d_out;
    (void)in_sizes; (void)n_in; (void)out_size;

    dim3 block(64, 4, 1);
    dim3 grid(HTILES, DCHUNKS, 1);
    grad_loss_fused<<<grid, block>>>(x1, x2, out);
}